// round 8
// baseline (speedup 1.0000x reference)
#include <cuda_runtime.h>
#include <cuda_bf16.h>
#include <cstdint>

#define NCH   8
#define TOPK  2
#define BSZ   4096
#define INF   4096
#define CIN   512
#define COUT  512
#define HID   1024
#define OUTF  4096

// ---------------- device scratch (no allocations allowed) ----------------
__device__ float g_act[NCH];          // zero-initialized at load; topk re-zeros after use
__device__ int   g_topk[TOPK];

__device__ __nv_bfloat16 g_xh[(size_t)TOPK * BSZ * CIN];
__device__ __nv_bfloat16 g_xl[(size_t)TOPK * BSZ * CIN];
__device__ __nv_bfloat16 g_wch[(size_t)TOPK * COUT * CIN];
__device__ __nv_bfloat16 g_wcl[(size_t)TOPK * COUT * CIN];
__device__ __nv_bfloat16 g_hh[(size_t)BSZ * HID];
__device__ __nv_bfloat16 g_hl[(size_t)BSZ * HID];
__device__ __nv_bfloat16 g_wfh[(size_t)OUTF * HID];
__device__ __nv_bfloat16 g_wfl[(size_t)OUTF * HID];

// ---------------- routing ----------------
__global__ void activity_kernel(const float* __restrict__ x) {
    float local[NCH];
#pragma unroll
    for (int c = 0; c < NCH; c++) local[c] = 0.0f;
    const long long total = (long long)BSZ * INF;
    const long long stride = (long long)gridDim.x * blockDim.x * 4;
    for (long long i = ((long long)blockIdx.x * blockDim.x + threadIdx.x) * 4; i < total; i += stride) {
        float4 v = *reinterpret_cast<const float4*>(x + i);
        int c = (int)((i >> 9) & 7);
        local[c] += fabsf(v.x) + fabsf(v.y) + fabsf(v.z) + fabsf(v.w);
    }
    __shared__ float sred[NCH];
    if (threadIdx.x < NCH) sred[threadIdx.x] = 0.0f;
    __syncthreads();
#pragma unroll
    for (int c = 0; c < NCH; c++) {
        float v = local[c];
#pragma unroll
        for (int off = 16; off > 0; off >>= 1) v += __shfl_xor_sync(0xffffffffu, v, off);
        if ((threadIdx.x & 31) == 0) atomicAdd(&sred[c], v);
    }
    __syncthreads();
    if (threadIdx.x < NCH) atomicAdd(&g_act[threadIdx.x], sred[threadIdx.x]);
}

__global__ void topk_kernel() {
    int best = 0;
#pragma unroll
    for (int i = 1; i < NCH; i++)
        if (g_act[i] > g_act[best]) best = i;
    int second = (best == 0) ? 1 : 0;
#pragma unroll
    for (int i = 0; i < NCH; i++)
        if (i != best && g_act[i] > g_act[second]) second = i;
    g_topk[0] = best;
    g_topk[1] = second;
#pragma unroll
    for (int i = 0; i < NCH; i++) g_act[i] = 0.0f;
}

// ---------------- fused conversion kernel ----------------
__device__ __forceinline__ void split2(float v, __nv_bfloat16& h, __nv_bfloat16& l) {
    h = __float2bfloat16(v);
    l = __float2bfloat16(v - __bfloat162float(h));
}

#define CVT_X_BLKS  4096
#define CVT_WC_BLKS 512
#define CVT_WF_BLKS 4096
#define CVT_TOTAL   (CVT_X_BLKS + CVT_WC_BLKS + CVT_WF_BLKS)

__global__ __launch_bounds__(256) void convert_all_kernel(
    const float* __restrict__ x,
    const float* __restrict__ Wc,
    const float* __restrict__ Wf)
{
    __shared__ float t[32][33];
    const int blk = blockIdx.x;

    if (blk < CVT_X_BLKS) {
        size_t g = (size_t)blk * 256 + threadIdx.x;
        int z = (int)(g >> 19);
        size_t r = g & 524287;
        int row = (int)(r >> 7);
        int c4  = (int)(r & 127);
        int chunk = g_topk[z];
        float4 v = __ldg((const float4*)(x + (size_t)row * INF + (size_t)chunk * CIN) + c4);
        __nv_bfloat16 h0, h1, h2, h3, l0, l1, l2, l3;
        split2(v.x, h0, l0); split2(v.y, h1, l1); split2(v.z, h2, l2); split2(v.w, h3, l3);
        size_t o = (size_t)z * BSZ * CIN + (size_t)row * CIN + (size_t)c4 * 4;
        *(ushort4*)(g_xh + o) = make_ushort4(__bfloat16_as_ushort(h0), __bfloat16_as_ushort(h1),
                                             __bfloat16_as_ushort(h2), __bfloat16_as_ushort(h3));
        *(ushort4*)(g_xl + o) = make_ushort4(__bfloat16_as_ushort(l0), __bfloat16_as_ushort(l1),
                                             __bfloat16_as_ushort(l2), __bfloat16_as_ushort(l3));
    } else if (blk < CVT_X_BLKS + CVT_WC_BLKS) {
        int idx = blk - CVT_X_BLKS;
        int z = idx >> 8, rem = idx & 255;
        int bx = rem & 15, by = rem >> 4;
        int tx = threadIdx.x & 31, ty = threadIdx.x >> 5;
        int chunk = g_topk[z];
        const float* W = Wc + (size_t)chunk * CIN * COUT;
#pragma unroll
        for (int i = 0; i < 4; i++)
            t[ty + i * 8][tx] = __ldg(W + (size_t)(by * 32 + ty + i * 8) * COUT + bx * 32 + tx);
        __syncthreads();
#pragma unroll
        for (int i = 0; i < 4; i++) {
            int nn = bx * 32 + ty + i * 8;
            int kk = by * 32 + tx;
            float v = t[tx][ty + i * 8];
            __nv_bfloat16 h, l; split2(v, h, l);
            size_t o = (size_t)z * COUT * CIN + (size_t)nn * CIN + kk;
            g_wch[o] = h; g_wcl[o] = l;
        }
    } else {
        int idx = blk - CVT_X_BLKS - CVT_WC_BLKS;
        int bx = idx & 127, by = idx >> 7;
        int tx = threadIdx.x & 31, ty = threadIdx.x >> 5;
#pragma unroll
        for (int i = 0; i < 4; i++)
            t[ty + i * 8][tx] = __ldg(Wf + (size_t)(by * 32 + ty + i * 8) * OUTF + bx * 32 + tx);
        __syncthreads();
#pragma unroll
        for (int i = 0; i < 4; i++) {
            int nn = bx * 32 + ty + i * 8;
            int kk = by * 32 + tx;
            float v = t[tx][ty + i * 8];
            __nv_bfloat16 h, l; split2(v, h, l);
            size_t o = (size_t)nn * HID + kk;
            g_wfh[o] = h; g_wfl[o] = l;
        }
    }
}

// ---------------- HMMA (mma.sync) bf16-split GEMM ----------------
#define STAGE_BYTES 32768
#define NSTAGES_BUF 3
#define SMEM_BYTES (NSTAGES_BUF * STAGE_BYTES)
#define OFF_AH 0
#define OFF_AL 8192
#define OFF_BH 16384
#define OFF_BL 24576

__device__ __forceinline__ uint32_t smem_u32(const void* p) {
    uint32_t a;
    asm("{ .reg .u64 t; cvta.to.shared.u64 t, %1; cvt.u32.u64 %0, t; }" : "=r"(a) : "l"(p));
    return a;
}
__device__ __forceinline__ void cp16(uint32_t sa, const void* ga) {
    asm volatile("cp.async.cg.shared.global [%0], [%1], 16;" :: "r"(sa), "l"(ga) : "memory");
}
__device__ __forceinline__ void ldm4(uint32_t* d, uint32_t a) {
    asm volatile("ldmatrix.sync.aligned.m8n8.x4.shared.b16 {%0,%1,%2,%3}, [%4];"
                 : "=r"(d[0]), "=r"(d[1]), "=r"(d[2]), "=r"(d[3]) : "r"(a));
}
__device__ __forceinline__ void mma16816(float* c, const uint32_t* a, uint32_t b0, uint32_t b1) {
    asm volatile(
        "mma.sync.aligned.m16n8k16.row.col.f32.bf16.bf16.f32 "
        "{%0,%1,%2,%3}, {%4,%5,%6,%7}, {%8,%9}, {%0,%1,%2,%3};"
        : "+f"(c[0]), "+f"(c[1]), "+f"(c[2]), "+f"(c[3])
        : "r"(a[0]), "r"(a[1]), "r"(a[2]), "r"(a[3]), "r"(b0), "r"(b1));
}

__device__ __forceinline__ void prefetch_stage(
    uint32_t sbase,
    const uint4* __restrict__ Ah, const uint4* __restrict__ Al,
    const uint4* __restrict__ Bh, const uint4* __restrict__ Bl,
    int ldv, int k0v)
{
    const int tid = threadIdx.x;
#pragma unroll
    for (int i = 0; i < 2; i++) {
        int c = tid + i * 256;
        int row = c >> 2, ch = c & 3;
        uint32_t so = (uint32_t)(row * 64 + ((ch ^ ((row >> 1) & 3)) << 4));
        size_t go = (size_t)row * ldv + k0v + ch;
        cp16(sbase + OFF_AH + so, Ah + go);
        cp16(sbase + OFF_AL + so, Al + go);
        cp16(sbase + OFF_BH + so, Bh + go);
        cp16(sbase + OFF_BL + so, Bl + go);
    }
    asm volatile("cp.async.commit_group;" ::: "memory");
}

__device__ __forceinline__ void mma_mainloop(
    const uint4* __restrict__ Ah, const uint4* __restrict__ Al,
    const uint4* __restrict__ Bh, const uint4* __restrict__ Bl,
    int ldv, int nStages, uint32_t smb, float acc[4][4][4])
{
    const int lane = threadIdx.x & 31;
    const int wid  = threadIdx.x >> 5;
    const int warp_m = wid & 1;
    const int warp_n = wid >> 1;
    const int r8 = lane & 7;

    const int aro = ((lane >> 3) & 1) * 8 + r8;
    const int acs = lane >> 4;
    const int bro = (lane >> 4) * 8 + r8;
    const int bcs = (lane >> 3) & 1;

    int arow[4], aswz[4];
#pragma unroll
    for (int mt = 0; mt < 4; mt++) {
        arow[mt] = warp_m * 64 + mt * 16 + aro;
        aswz[mt] = (arow[mt] >> 1) & 3;
    }
    int brow[2], bswz[2];
#pragma unroll
    for (int np = 0; np < 2; np++) {
        brow[np] = warp_n * 32 + np * 16 + bro;
        bswz[np] = (brow[np] >> 1) & 3;
    }

    prefetch_stage(smb, Ah, Al, Bh, Bl, ldv, 0);
    prefetch_stage(smb + STAGE_BYTES, Ah, Al, Bh, Bl, ldv, 4);

    for (int s = 0; s < nStages; s++) {
        asm volatile("cp.async.wait_group 1;" ::: "memory");
        __syncthreads();

        if (s + 2 < nStages)
            prefetch_stage(smb + ((s + 2) % NSTAGES_BUF) * STAGE_BYTES,
                           Ah, Al, Bh, Bl, ldv, (s + 2) * 4);
        else
            asm volatile("cp.async.commit_group;" ::: "memory");

        uint32_t st = smb + (s % NSTAGES_BUF) * STAGE_BYTES;

        uint32_t bh[2][4], bl[2][4];
        uint32_t ab[2][8];   // double-buffered A fragments

        // load B frags for ks=0
#pragma unroll
        for (int np = 0; np < 2; np++) {
            uint32_t bo = (uint32_t)(brow[np] * 64 + ((bcs ^ bswz[np]) << 4));
            ldm4(bh[np], st + OFF_BH + bo);
            ldm4(bl[np], st + OFF_BL + bo);
        }
        // load A frag for step 0
        {
            uint32_t ao = (uint32_t)(arow[0] * 64 + ((acs ^ aswz[0]) << 4));
            ldm4(&ab[0][0], st + OFF_AH + ao);
            ldm4(&ab[0][4], st + OFF_AL + ao);
        }

#pragma unroll
        for (int i = 0; i < 8; i++) {
            const int cur = i & 1;
            if (i == 4) {
#pragma unroll
                for (int np = 0; np < 2; np++) {
                    uint32_t bo = (uint32_t)(brow[np] * 64 + (((2 + bcs) ^ bswz[np]) << 4));
                    ldm4(bh[np], st + OFF_BH + bo);
                    ldm4(bl[np], st + OFF_BL + bo);
                }
            }
            if (i < 7) {
                const int ni = i + 1;
                const int nks = ni >> 2, nmt = ni & 3;
                uint32_t ao = (uint32_t)(arow[nmt] * 64 + (((nks * 2 + acs) ^ aswz[nmt]) << 4));
                ldm4(&ab[ni & 1][0], st + OFF_AH + ao);
                ldm4(&ab[ni & 1][4], st + OFF_AL + ao);
            }
            const int mt = i & 3;
            const uint32_t* ah = &ab[cur][0];
            const uint32_t* al = &ab[cur][4];
            // product-major issue: dependent writes to any acc are 4 issues apart
#pragma unroll
            for (int nt = 0; nt < 4; nt++)
                mma16816(acc[mt][nt], ah, bh[nt >> 1][(nt & 1) * 2], bh[nt >> 1][(nt & 1) * 2 + 1]);
#pragma unroll
            for (int nt = 0; nt < 4; nt++)
                mma16816(acc[mt][nt], ah, bl[nt >> 1][(nt & 1) * 2], bl[nt >> 1][(nt & 1) * 2 + 1]);
#pragma unroll
            for (int nt = 0; nt < 4; nt++)
                mma16816(acc[mt][nt], al, bh[nt >> 1][(nt & 1) * 2], bh[nt >> 1][(nt & 1) * 2 + 1]);
        }
        // no bottom barrier: next top barrier orders compute(s) vs prefetch into s buffer
    }
}

// GEMM1: h[:, z*512 + bx*128 ..] = x_sel[z] @ Wc[z]^T + bc ; emits bf16 hi/lo
__global__ __launch_bounds__(256, 2) void gemm1_kernel(const float* __restrict__ bc) {
    extern __shared__ char sm[];
    uint32_t smb = smem_u32(sm);
    const int bx = blockIdx.x, by = blockIdx.y, z = blockIdx.z;
    const int chunk = g_topk[z];

    const uint4* Ah = (const uint4*)(g_xh + (size_t)z * BSZ * CIN + (size_t)by * 128 * CIN);
    const uint4* Al = (const uint4*)(g_xl + (size_t)z * BSZ * CIN + (size_t)by * 128 * CIN);
    const uint4* Bh = (const uint4*)(g_wch + (size_t)z * COUT * CIN + (size_t)bx * 128 * CIN);
    const uint4* Bl = (const uint4*)(g_wcl + (size_t)z * COUT * CIN + (size_t)bx * 128 * CIN);

    float acc[4][4][4];
#pragma unroll
    for (int a = 0; a < 4; a++)
#pragma unroll
        for (int b = 0; b < 4; b++)
#pragma unroll
            for (int c = 0; c < 4; c++) acc[a][b][c] = 0.0f;

    mma_mainloop(Ah, Al, Bh, Bl, CIN / 8, CIN / 32, smb, acc);

    const int lane = threadIdx.x & 31, wid = threadIdx.x >> 5;
    const int warp_m = wid & 1, warp_n = wid >> 1;
    const int g = lane >> 2, tg = lane & 3;
#pragma unroll
    for (int mt = 0; mt < 4; mt++) {
#pragma unroll
        for (int nt = 0; nt < 4; nt++) {
            int cl = warp_n * 32 + nt * 8 + tg * 2;
            int colg = z * COUT + bx * 128 + cl;
            float b0 = __ldg(bc + (size_t)chunk * COUT + bx * 128 + cl);
            float b1 = __ldg(bc + (size_t)chunk * COUT + bx * 128 + cl + 1);
#pragma unroll
            for (int half = 0; half < 2; half++) {
                int row = by * 128 + warp_m * 64 + mt * 16 + g + half * 8;
                float v0 = acc[mt][nt][half * 2 + 0] + b0;
                float v1 = acc[mt][nt][half * 2 + 1] + b1;
                __nv_bfloat16 h0, l0, h1, l1;
                split2(v0, h0, l0); split2(v1, h1, l1);
                size_t o = (size_t)row * HID + colg;
                *(ushort2*)(g_hh + o) = make_ushort2(__bfloat16_as_ushort(h0), __bfloat16_as_ushort(h1));
                *(ushort2*)(g_hl + o) = make_ushort2(__bfloat16_as_ushort(l0), __bfloat16_as_ushort(l1));
            }
        }
    }
}

// GEMM2: out = h @ W_final + b_final. Persistent CTAs over 1024 tiles.
#define G2_TILES 1024
#define G2_GRID  296

__global__ __launch_bounds__(256, 2) void gemm2_kernel(const float* __restrict__ bf,
                                                       float* __restrict__ out) {
    extern __shared__ char sm[];
    uint32_t smb = smem_u32(sm);

    const int lane = threadIdx.x & 31, wid = threadIdx.x >> 5;
    const int warp_m = wid & 1, warp_n = wid >> 1;
    const int g = lane >> 2, tg = lane & 3;

    for (int tile = blockIdx.x; tile < G2_TILES; tile += G2_GRID) {
        const int bx = tile & 31, by = tile >> 5;

        const uint4* Ah = (const uint4*)(g_hh + (size_t)by * 128 * HID);
        const uint4* Al = (const uint4*)(g_hl + (size_t)by * 128 * HID);
        const uint4* Bh = (const uint4*)(g_wfh + (size_t)bx * 128 * HID);
        const uint4* Bl = (const uint4*)(g_wfl + (size_t)bx * 128 * HID);

        float acc[4][4][4];
#pragma unroll
        for (int a = 0; a < 4; a++)
#pragma unroll
            for (int b = 0; b < 4; b++)
#pragma unroll
                for (int c = 0; c < 4; c++) acc[a][b][c] = 0.0f;

        mma_mainloop(Ah, Al, Bh, Bl, HID / 8, HID / 32, smb, acc);

#pragma unroll
        for (int mt = 0; mt < 4; mt++) {
#pragma unroll
            for (int nt = 0; nt < 4; nt++) {
                int col = bx * 128 + warp_n * 32 + nt * 8 + tg * 2;
                float b0 = __ldg(bf + col);
                float b1 = __ldg(bf + col + 1);
#pragma unroll
                for (int half = 0; half < 2; half++) {
                    int row = by * 128 + warp_m * 64 + mt * 16 + g + half * 8;
                    float2 v;
                    v.x = acc[mt][nt][half * 2 + 0] + b0;
                    v.y = acc[mt][nt][half * 2 + 1] + b1;
                    *(float2*)(out + (size_t)row * OUTF + col) = v;
                }
            }
        }
        // protect smem stage buffers: slow warps may still be reading the last
        // stage while a fast warp would start the next tile's prefetch.
        __syncthreads();
    }
}

// ---------------- launcher ----------------
extern "C" void kernel_launch(void* const* d_in, const int* in_sizes, int n_in,
                              void* d_out, int out_size)
{
    const float* x  = (const float*)d_in[0];
    const float* Wc = (const float*)d_in[1];
    const float* bc = (const float*)d_in[2];
    const float* Wf = (const float*)d_in[3];
    const float* bf = (const float*)d_in[4];
    float* out = (float*)d_out;

    cudaFuncSetAttribute(gemm1_kernel, cudaFuncAttributeMaxDynamicSharedMemorySize, SMEM_BYTES);
    cudaFuncSetAttribute(gemm2_kernel, cudaFuncAttributeMaxDynamicSharedMemorySize, SMEM_BYTES);

    activity_kernel<<<2048, 256>>>(x);                 // 1
    topk_kernel<<<1, 1>>>();                           // 2
    convert_all_kernel<<<CVT_TOTAL, 256>>>(x, Wc, Wf); // 3
    gemm1_kernel<<<dim3(4, 32, 2), 256, SMEM_BYTES>>>(bc);    // 4 (profiled)
    gemm2_kernel<<<G2_GRID, 256, SMEM_BYTES>>>(bf, out);      // 5
}

// round 10
// speedup vs baseline: 1.3664x; 1.3664x over previous
#include <cuda_runtime.h>
#include <cuda_bf16.h>
#include <cuda_fp16.h>
#include <cstdint>

#define NCH   8
#define TOPK  2
#define BSZ   4096
#define INF   4096
#define CIN   512
#define COUT  512
#define HID   1024
#define OUTF  4096

// ---------------- device scratch (no allocations allowed) ----------------
__device__ float g_act[NCH];          // zero-initialized at load; topk re-zeros after use
__device__ int   g_topk[TOPK];

__device__ __half g_xh[(size_t)TOPK * BSZ * CIN];     // x selected, fp16 hi
__device__ __half g_xl[(size_t)TOPK * BSZ * CIN];     // x selected, fp16 lo
__device__ __half g_wc[(size_t)TOPK * COUT * CIN];    // W_chunk^T fp16 [N][K]
__device__ __half g_hh[(size_t)BSZ * HID];            // h fp16 hi
__device__ __half g_hl[(size_t)BSZ * HID];            // h fp16 lo
__device__ __half g_wf[(size_t)OUTF * HID];           // W_final^T fp16 [N][K]

// ---------------- routing ----------------
__global__ void activity_kernel(const float* __restrict__ x) {
    float local[NCH];
#pragma unroll
    for (int c = 0; c < NCH; c++) local[c] = 0.0f;
    const long long total = (long long)BSZ * INF;
    const long long stride = (long long)gridDim.x * blockDim.x * 4;
    for (long long i = ((long long)blockIdx.x * blockDim.x + threadIdx.x) * 4; i < total; i += stride) {
        float4 v = *reinterpret_cast<const float4*>(x + i);
        int c = (int)((i >> 9) & 7);
        local[c] += fabsf(v.x) + fabsf(v.y) + fabsf(v.z) + fabsf(v.w);
    }
    __shared__ float sred[NCH];
    if (threadIdx.x < NCH) sred[threadIdx.x] = 0.0f;
    __syncthreads();
#pragma unroll
    for (int c = 0; c < NCH; c++) {
        float v = local[c];
#pragma unroll
        for (int off = 16; off > 0; off >>= 1) v += __shfl_xor_sync(0xffffffffu, v, off);
        if ((threadIdx.x & 31) == 0) atomicAdd(&sred[c], v);
    }
    __syncthreads();
    if (threadIdx.x < NCH) atomicAdd(&g_act[threadIdx.x], sred[threadIdx.x]);
}

__global__ void topk_kernel() {
    int best = 0;
#pragma unroll
    for (int i = 1; i < NCH; i++)
        if (g_act[i] > g_act[best]) best = i;
    int second = (best == 0) ? 1 : 0;
#pragma unroll
    for (int i = 0; i < NCH; i++)
        if (i != best && g_act[i] > g_act[second]) second = i;
    g_topk[0] = best;
    g_topk[1] = second;
#pragma unroll
    for (int i = 0; i < NCH; i++) g_act[i] = 0.0f;
}

// ---------------- conversions ----------------
__device__ __forceinline__ void split2h(float v, __half& h, __half& l) {
    h = __float2half_rn(v);
    l = __float2half_rn(v - __half2float(h));
}

// blocks [0,4096): x -> fp16 hi/lo ; [4096,4608): Wc^T fp16 ; [4608,8704): Wf^T fp16
#define CVT_X_BLKS  4096
#define CVT_WC_BLKS 512
#define CVT_WF_BLKS 4096
#define CVT_TOTAL   (CVT_X_BLKS + CVT_WC_BLKS + CVT_WF_BLKS)

__global__ __launch_bounds__(256) void convert_all_kernel(
    const float* __restrict__ x,
    const float* __restrict__ Wc,
    const float* __restrict__ Wf)
{
    __shared__ float t[32][33];
    const int blk = blockIdx.x;

    if (blk < CVT_X_BLKS) {
        size_t g = (size_t)blk * 256 + threadIdx.x;     // 2*4096*128 float4-groups
        int z = (int)(g >> 19);
        size_t r = g & 524287;
        int row = (int)(r >> 7);
        int c4  = (int)(r & 127);
        int chunk = g_topk[z];
        float4 v = __ldg((const float4*)(x + (size_t)row * INF + (size_t)chunk * CIN) + c4);
        __half h0, h1, h2, h3, l0, l1, l2, l3;
        split2h(v.x, h0, l0); split2h(v.y, h1, l1); split2h(v.z, h2, l2); split2h(v.w, h3, l3);
        size_t o = (size_t)z * BSZ * CIN + (size_t)row * CIN + (size_t)c4 * 4;
        *(ushort4*)(g_xh + o) = make_ushort4(__half_as_ushort(h0), __half_as_ushort(h1),
                                             __half_as_ushort(h2), __half_as_ushort(h3));
        *(ushort4*)(g_xl + o) = make_ushort4(__half_as_ushort(l0), __half_as_ushort(l1),
                                             __half_as_ushort(l2), __half_as_ushort(l3));
    } else if (blk < CVT_X_BLKS + CVT_WC_BLKS) {
        int idx = blk - CVT_X_BLKS;
        int z = idx >> 8, rem = idx & 255;
        int bx = rem & 15, by = rem >> 4;
        int tx = threadIdx.x & 31, ty = threadIdx.x >> 5;
        int chunk = g_topk[z];
        const float* W = Wc + (size_t)chunk * CIN * COUT;
#pragma unroll
        for (int i = 0; i < 4; i++)
            t[ty + i * 8][tx] = __ldg(W + (size_t)(by * 32 + ty + i * 8) * COUT + bx * 32 + tx);
        __syncthreads();
#pragma unroll
        for (int i = 0; i < 4; i++) {
            int nn = bx * 32 + ty + i * 8;
            int kk = by * 32 + tx;
            g_wc[(size_t)z * COUT * CIN + (size_t)nn * CIN + kk] = __float2half_rn(t[tx][ty + i * 8]);
        }
    } else {
        int idx = blk - CVT_X_BLKS - CVT_WC_BLKS;
        int bx = idx & 127, by = idx >> 7;
        int tx = threadIdx.x & 31, ty = threadIdx.x >> 5;
#pragma unroll
        for (int i = 0; i < 4; i++)
            t[ty + i * 8][tx] = __ldg(Wf + (size_t)(by * 32 + ty + i * 8) * OUTF + bx * 32 + tx);
        __syncthreads();
#pragma unroll
        for (int i = 0; i < 4; i++) {
            int nn = bx * 32 + ty + i * 8;
            int kk = by * 32 + tx;
            g_wf[(size_t)nn * HID + kk] = __float2half_rn(t[tx][ty + i * 8]);
        }
    }
}

// ---------------- HMMA (mma.sync) fp16-split GEMM ----------------
// C = (Ah + Al) @ B^T : 2 products per fragment pair (W is plain fp16).
// CTA tile 128x128, BK=32, 8 warps, warp tile 64x32. 4-stage cp.async pipeline
// (depth-3 prefetch), 2 CTAs/SM. Stage = Ah(8K) + Al(8K) + B(8K) = 24KB.

#define STAGE_BYTES 24576
#define NSTAGES_BUF 4
#define SMEM_BYTES (NSTAGES_BUF * STAGE_BYTES)
#define OFF_AH 0
#define OFF_AL 8192
#define OFF_B  16384

__device__ __forceinline__ uint32_t smem_u32(const void* p) {
    uint32_t a;
    asm("{ .reg .u64 t; cvta.to.shared.u64 t, %1; cvt.u32.u64 %0, t; }" : "=r"(a) : "l"(p));
    return a;
}
__device__ __forceinline__ void cp16(uint32_t sa, const void* ga) {
    asm volatile("cp.async.cg.shared.global [%0], [%1], 16;" :: "r"(sa), "l"(ga) : "memory");
}
__device__ __forceinline__ void ldm4(uint32_t* d, uint32_t a) {
    asm volatile("ldmatrix.sync.aligned.m8n8.x4.shared.b16 {%0,%1,%2,%3}, [%4];"
                 : "=r"(d[0]), "=r"(d[1]), "=r"(d[2]), "=r"(d[3]) : "r"(a));
}
__device__ __forceinline__ void mma16816(float* c, const uint32_t* a, uint32_t b0, uint32_t b1) {
    asm volatile(
        "mma.sync.aligned.m16n8k16.row.col.f32.f16.f16.f32 "
        "{%0,%1,%2,%3}, {%4,%5,%6,%7}, {%8,%9}, {%0,%1,%2,%3};"
        : "+f"(c[0]), "+f"(c[1]), "+f"(c[2]), "+f"(c[3])
        : "r"(a[0]), "r"(a[1]), "r"(a[2]), "r"(a[3]), "r"(b0), "r"(b1));
}

// prefetch one BK=32 stage. ldv = K/8 (uint4 stride), k0v = k0/8.
__device__ __forceinline__ void prefetch_stage(
    uint32_t sbase,
    const uint4* __restrict__ Ah, const uint4* __restrict__ Al,
    const uint4* __restrict__ B,
    int ldv, int k0v)
{
    const int tid = threadIdx.x;
#pragma unroll
    for (int i = 0; i < 2; i++) {
        int c = tid + i * 256;          // 0..511
        int row = c >> 2, ch = c & 3;
        uint32_t so = (uint32_t)(row * 64 + ((ch ^ ((row >> 1) & 3)) << 4));
        size_t go = (size_t)row * ldv + k0v + ch;
        cp16(sbase + OFF_AH + so, Ah + go);
        cp16(sbase + OFF_AL + so, Al + go);
        cp16(sbase + OFF_B  + so, B  + go);
    }
    asm volatile("cp.async.commit_group;" ::: "memory");
}

__device__ __forceinline__ void mma_mainloop(
    const uint4* __restrict__ Ah, const uint4* __restrict__ Al,
    const uint4* __restrict__ B,
    int ldv, int nStages, uint32_t smb, float acc[4][4][4])
{
    const int lane = threadIdx.x & 31;
    const int wid  = threadIdx.x >> 5;
    const int warp_m = wid & 1;
    const int warp_n = wid >> 1;
    const int r8 = lane & 7;

    const int aro = ((lane >> 3) & 1) * 8 + r8;   // A row offset within m16
    const int acs = lane >> 4;                    // A chunk select
    const int bro = (lane >> 4) * 8 + r8;         // B row offset within n16
    const int bcs = (lane >> 3) & 1;              // B chunk select

    int arow[4], aswz[4];
#pragma unroll
    for (int mt = 0; mt < 4; mt++) {
        arow[mt] = warp_m * 64 + mt * 16 + aro;
        aswz[mt] = (arow[mt] >> 1) & 3;
    }
    int brow[2], bswz[2];
#pragma unroll
    for (int np = 0; np < 2; np++) {
        brow[np] = warp_n * 32 + np * 16 + bro;
        bswz[np] = (brow[np] >> 1) & 3;
    }

    // depth-3 prologue
    prefetch_stage(smb + 0 * STAGE_BYTES, Ah, Al, B, ldv, 0);
    prefetch_stage(smb + 1 * STAGE_BYTES, Ah, Al, B, ldv, 4);
    prefetch_stage(smb + 2 * STAGE_BYTES, Ah, Al, B, ldv, 8);

    for (int s = 0; s < nStages; s++) {
        asm volatile("cp.async.wait_group 2;" ::: "memory");
        __syncthreads();

        if (s + 3 < nStages)
            prefetch_stage(smb + ((s + 3) % NSTAGES_BUF) * STAGE_BYTES,
                           Ah, Al, B, ldv, (s + 3) * 4);
        else
            asm volatile("cp.async.commit_group;" ::: "memory");

        uint32_t st = smb + (s % NSTAGES_BUF) * STAGE_BYTES;

        uint32_t bfr[2][4];
        uint32_t ab[2][8];   // double-buffered A fragments [buf][ah0..3, al0..3]

        // B frags for ks=0
#pragma unroll
        for (int np = 0; np < 2; np++) {
            uint32_t bo = (uint32_t)(brow[np] * 64 + ((bcs ^ bswz[np]) << 4));
            ldm4(bfr[np], st + OFF_B + bo);
        }
        // A frag for step 0
        {
            uint32_t ao = (uint32_t)(arow[0] * 64 + ((acs ^ aswz[0]) << 4));
            ldm4(&ab[0][0], st + OFF_AH + ao);
            ldm4(&ab[0][4], st + OFF_AL + ao);
        }

#pragma unroll
        for (int i = 0; i < 8; i++) {
            const int cur = i & 1;
            if (i == 4) {
#pragma unroll
                for (int np = 0; np < 2; np++) {
                    uint32_t bo = (uint32_t)(brow[np] * 64 + (((2 + bcs) ^ bswz[np]) << 4));
                    ldm4(bfr[np], st + OFF_B + bo);
                }
            }
            if (i < 7) {
                const int ni = i + 1;
                const int nks = ni >> 2, nmt = ni & 3;
                uint32_t ao = (uint32_t)(arow[nmt] * 64 + (((nks * 2 + acs) ^ aswz[nmt]) << 4));
                ldm4(&ab[ni & 1][0], st + OFF_AH + ao);
                ldm4(&ab[ni & 1][4], st + OFF_AL + ao);
            }
            const int mt = i & 3;
            const uint32_t* ah = &ab[cur][0];
            const uint32_t* al = &ab[cur][4];
            // product-major: same-acc writes 4 issues apart
#pragma unroll
            for (int nt = 0; nt < 4; nt++)
                mma16816(acc[mt][nt], ah, bfr[nt >> 1][(nt & 1) * 2], bfr[nt >> 1][(nt & 1) * 2 + 1]);
#pragma unroll
            for (int nt = 0; nt < 4; nt++)
                mma16816(acc[mt][nt], al, bfr[nt >> 1][(nt & 1) * 2], bfr[nt >> 1][(nt & 1) * 2 + 1]);
        }
        // single barrier per stage (top of next iteration protects buffer reuse)
    }
}

// GEMM1: h[:, z*512 + bx*128 ..] = x_sel[z] @ Wc[z]^T + bc ; emits fp16 hi/lo
__global__ __launch_bounds__(256, 2) void gemm1_kernel(const float* __restrict__ bc) {
    extern __shared__ char sm[];
    uint32_t smb = smem_u32(sm);
    const int bx = blockIdx.x, by = blockIdx.y, z = blockIdx.z;
    const int chunk = g_topk[z];

    const uint4* Ah = (const uint4*)(g_xh + (size_t)z * BSZ * CIN + (size_t)by * 128 * CIN);
    const uint4* Al = (const uint4*)(g_xl + (size_t)z * BSZ * CIN + (size_t)by * 128 * CIN);
    const uint4* B  = (const uint4*)(g_wc + (size_t)z * COUT * CIN + (size_t)bx * 128 * CIN);

    float acc[4][4][4];
#pragma unroll
    for (int a = 0; a < 4; a++)
#pragma unroll
        for (int b = 0; b < 4; b++)
#pragma unroll
            for (int c = 0; c < 4; c++) acc[a][b][c] = 0.0f;

    mma_mainloop(Ah, Al, B, CIN / 8, CIN / 32, smb, acc);

    const int lane = threadIdx.x & 31, wid = threadIdx.x >> 5;
    const int warp_m = wid & 1, warp_n = wid >> 1;
    const int g = lane >> 2, tg = lane & 3;
#pragma unroll
    for (int mt = 0; mt < 4; mt++) {
#pragma unroll
        for (int nt = 0; nt < 4; nt++) {
            int cl = warp_n * 32 + nt * 8 + tg * 2;
            int colg = z * COUT + bx * 128 + cl;
            float b0 = __ldg(bc + (size_t)chunk * COUT + bx * 128 + cl);
            float b1 = __ldg(bc + (size_t)chunk * COUT + bx * 128 + cl + 1);
#pragma unroll
            for (int half = 0; half < 2; half++) {
                int row = by * 128 + warp_m * 64 + mt * 16 + g + half * 8;
                float v0 = acc[mt][nt][half * 2 + 0] + b0;
                float v1 = acc[mt][nt][half * 2 + 1] + b1;
                __half h0, l0, h1, l1;
                split2h(v0, h0, l0); split2h(v1, h1, l1);
                size_t o = (size_t)row * HID + colg;
                *(ushort2*)(g_hh + o) = make_ushort2(__half_as_ushort(h0), __half_as_ushort(h1));
                *(ushort2*)(g_hl + o) = make_ushort2(__half_as_ushort(l0), __half_as_ushort(l1));
            }
        }
    }
}

// GEMM2: out = h @ W_final + b_final
__global__ __launch_bounds__(256, 2) void gemm2_kernel(const float* __restrict__ bf,
                                                       float* __restrict__ out) {
    extern __shared__ char sm[];
    uint32_t smb = smem_u32(sm);
    const int bx = blockIdx.x, by = blockIdx.y;

    const uint4* Ah = (const uint4*)(g_hh + (size_t)by * 128 * HID);
    const uint4* Al = (const uint4*)(g_hl + (size_t)by * 128 * HID);
    const uint4* B  = (const uint4*)(g_wf + (size_t)bx * 128 * HID);

    float acc[4][4][4];
#pragma unroll
    for (int a = 0; a < 4; a++)
#pragma unroll
        for (int b = 0; b < 4; b++)
#pragma unroll
            for (int c = 0; c < 4; c++) acc[a][b][c] = 0.0f;

    mma_mainloop(Ah, Al, B, HID / 8, HID / 32, smb, acc);

    const int lane = threadIdx.x & 31, wid = threadIdx.x >> 5;
    const int warp_m = wid & 1, warp_n = wid >> 1;
    const int g = lane >> 2, tg = lane & 3;
#pragma unroll
    for (int mt = 0; mt < 4; mt++) {
#pragma unroll
        for (int nt = 0; nt < 4; nt++) {
            int col = bx * 128 + warp_n * 32 + nt * 8 + tg * 2;
            float b0 = __ldg(bf + col);
            float b1 = __ldg(bf + col + 1);
#pragma unroll
            for (int half = 0; half < 2; half++) {
                int row = by * 128 + warp_m * 64 + mt * 16 + g + half * 8;
                float2 v;
                v.x = acc[mt][nt][half * 2 + 0] + b0;
                v.y = acc[mt][nt][half * 2 + 1] + b1;
                *(float2*)(out + (size_t)row * OUTF + col) = v;
            }
        }
    }
}

// ---------------- launcher ----------------
extern "C" void kernel_launch(void* const* d_in, const int* in_sizes, int n_in,
                              void* d_out, int out_size)
{
    const float* x  = (const float*)d_in[0];
    const float* Wc = (const float*)d_in[1];
    const float* bc = (const float*)d_in[2];
    const float* Wf = (const float*)d_in[3];
    const float* bf = (const float*)d_in[4];
    float* out = (float*)d_out;

    cudaFuncSetAttribute(gemm1_kernel, cudaFuncAttributeMaxDynamicSharedMemorySize, SMEM_BYTES);
    cudaFuncSetAttribute(gemm2_kernel, cudaFuncAttributeMaxDynamicSharedMemorySize, SMEM_BYTES);

    activity_kernel<<<2048, 256>>>(x);                 // 1
    topk_kernel<<<1, 1>>>();                           // 2
    convert_all_kernel<<<CVT_TOTAL, 256>>>(x, Wc, Wf); // 3
    gemm1_kernel<<<dim3(4, 32, 2), 256, SMEM_BYTES>>>(bc);    // 4 (profiled)
    gemm2_kernel<<<dim3(32, 32), 256, SMEM_BYTES>>>(bf, out); // 5
}